// round 3
// baseline (speedup 1.0000x reference)
#include <cuda_runtime.h>
#include <cuda_bf16.h>
#include <cstdint>

// Only Z0[:,:,-1] = conv(X0, t=10) is nonzero in the output.
// Needs: h3 rows t=9,10 ; U feats 9,10,11 ; 3 adjacencies (a=10,9,11 ; c=10).
// Softmax degree-normalization in norm_adj is an exact no-op.

// ---------------- device scratch ----------------
__device__ float g_obs2[2 * 8192];     // MLP input rows t=9,10
__device__ float g_s1[2 * 2048];
__device__ float g_h1[2 * 2048];
__device__ float g_s2[2 * 2048];
__device__ float g_h2[2 * 2048];
__device__ float g_s3[2 * 12288];
__device__ float g_h3[2 * 12288];      // row0 = X9 (1024x12), row1 = X10
__device__ float g_sph[12 * 256];
__device__ float g_tph[256];
__device__ float g_U[3 * 1024 * 12];   // [c][n][tau], c = feat-9
__device__ float g_Y[1024 * 12];       // Y[n][p] = sum_q B[p,q]*U[n,q,10]

// ---------------- prep: gather obs rows, init s1 = b1, zero output tail ----
__global__ void prep_kernel(const float* __restrict__ obs,
                            const float* __restrict__ b1,
                            float* __restrict__ out) {
    int idx = blockIdx.x * blockDim.x + threadIdx.x;
    if (idx < 16384) {
        int m = idx >> 13;          // 0 -> t=9, 1 -> t=10
        int k = idx & 8191;         // n*8 + d
        int n = k >> 3, d = k & 7;
        g_obs2[idx] = obs[n * 96 + d * 12 + 9 + m];
    }
    int i2 = idx - 16384;
    if (i2 >= 0 && i2 < 4096) g_s1[i2] = b1[i2 & 2047];
    int i3 = idx - 20480;
    if (i3 >= 0 && i3 < 36864) out[12288 + i3] = 0.0f;
}

// ---------------- split-K GEMV (M=2), atomic accumulate into bias-init scratch
template<int K, int N>
__device__ __forceinline__ void gemv_body(const float* __restrict__ A,
                                          const float* __restrict__ W,
                                          float* __restrict__ S, int kchunk) {
    int col = (blockIdx.x * blockDim.x + threadIdx.x) * 4;
    int k0  = blockIdx.y * kchunk;
    float a00 = 0, a01 = 0, a02 = 0, a03 = 0;
    float a10 = 0, a11 = 0, a12 = 0, a13 = 0;
#pragma unroll 8
    for (int k = k0; k < k0 + kchunk; ++k) {
        const float4 w = *reinterpret_cast<const float4*>(W + (size_t)k * N + col);
        float x0 = A[k], x1 = A[K + k];
        a00 += x0 * w.x; a01 += x0 * w.y; a02 += x0 * w.z; a03 += x0 * w.w;
        a10 += x1 * w.x; a11 += x1 * w.y; a12 += x1 * w.z; a13 += x1 * w.w;
    }
    atomicAdd(S + col + 0, a00); atomicAdd(S + col + 1, a01);
    atomicAdd(S + col + 2, a02); atomicAdd(S + col + 3, a03);
    atomicAdd(S + N + col + 0, a10); atomicAdd(S + N + col + 1, a11);
    atomicAdd(S + N + col + 2, a12); atomicAdd(S + N + col + 3, a13);
}

__global__ void gemv1_kernel(const float* __restrict__ W, int kchunk) {
    gemv_body<8192, 2048>(g_obs2, W, g_s1, kchunk);
}
__global__ void gemv2_kernel(const float* __restrict__ W, int kchunk) {
    gemv_body<2048, 2048>(g_h1, W, g_s2, kchunk);
}
__global__ void gemv3_kernel(const float* __restrict__ W, int kchunk) {
    gemv_body<2048, 12288>(g_h2, W, g_s3, kchunk);
}

// ---------------- activation + init next scratch ----------------
__global__ void act1_kernel(const float* __restrict__ b2) {
    int idx = blockIdx.x * blockDim.x + threadIdx.x;
    if (idx < 4096) {
        g_h1[idx] = fmaxf(g_s1[idx], 0.0f);
        g_s2[idx] = b2[idx & 2047];
    }
}
__global__ void act2_kernel(const float* __restrict__ b3) {
    int idx = blockIdx.x * blockDim.x + threadIdx.x;
    if (idx < 4096) g_h2[idx] = fmaxf(g_s2[idx], 0.0f);
    if (idx < 24576) g_s3[idx] = b3[idx % 12288];
}
__global__ void act3_kernel() {
    int idx = blockIdx.x * blockDim.x + threadIdx.x;
    if (idx < 24576) g_h3[idx] = fmaxf(g_s3[idx], 0.0f);
}

// ---------------- small hidden layers: sph (12x256), tph (256) -------------
__global__ void small_hidden_kernel(const float* __restrict__ li,
                                    const float* __restrict__ gs_w1,
                                    const float* __restrict__ gs_b1,
                                    const float* __restrict__ tf,
                                    const float* __restrict__ gt_w1,
                                    const float* __restrict__ gt_b1) {
    int t = threadIdx.x;
    if (blockIdx.x < 12) {
        const float* row = li + blockIdx.x * 1024;
        float acc = 0.0f;
#pragma unroll 4
        for (int k = 0; k < 1024; ++k) acc += row[k] * gs_w1[k * 256 + t];
        g_sph[blockIdx.x * 256 + t] = fmaxf(acc + gs_b1[t], 0.0f);
    } else {
        float acc = 0.0f;
#pragma unroll
        for (int k = 0; k < 36; ++k) acc += tf[k] * gt_w1[k * 256 + t];
        g_tph[t] = fmaxf(acc + gt_b1[t], 0.0f);
    }
}

// ---------------- U features 9,10,11 : 1024 blocks x 96 threads ------------
__global__ void u_kernel(const float* __restrict__ gs_w2,
                         const float* __restrict__ gs_b2,
                         const float* __restrict__ gt_w2,
                         const float* __restrict__ gt_b2) {
    int n = blockIdx.x;
    int c = threadIdx.x >> 5;       // 0..2 -> feats 9..11
    int lane = threadIdx.x & 31;
    int j = n * 12 + 9 + c;
    float wg[8], wt[8];
#pragma unroll
    for (int i = 0; i < 8; ++i) {
        int k = lane + 32 * i;
        wg[i] = gs_w2[(size_t)k * 12288 + j];
        wt[i] = gt_w2[(size_t)k * 12288 + j];
    }
    float tp = 0.0f;
#pragma unroll
    for (int i = 0; i < 8; ++i) tp += g_tph[lane + 32 * i] * wt[i];
#pragma unroll
    for (int o = 16; o; o >>= 1) tp += __shfl_xor_sync(0xffffffff, tp, o);
    float tpv = fmaxf(tp + gt_b2[j], 0.0f);
    float bsp = gs_b2[j];
#pragma unroll
    for (int tau = 0; tau < 12; ++tau) {
        float sp = 0.0f;
#pragma unroll
        for (int i = 0; i < 8; ++i) sp += g_sph[tau * 256 + lane + 32 * i] * wg[i];
#pragma unroll
        for (int o = 16; o; o >>= 1) sp += __shfl_xor_sync(0xffffffff, sp, o);
        if (lane == 0)
            g_U[c * 12288 + n * 12 + tau] = fmaxf(sp + bsp, 0.0f) + tpv;
    }
}

// ---------------- Y = U_10 @ B^T ----------------
__global__ void y_kernel(const float* __restrict__ Bm) {
    int idx = blockIdx.x * blockDim.x + threadIdx.x;
    if (idx >= 12288) return;
    int n = idx / 12, p = idx % 12;
    float acc = 0.0f;
#pragma unroll
    for (int q = 0; q < 12; ++q)
        acc += Bm[p * 12 + q] * g_U[12288 + n * 12 + q];
    g_Y[idx] = acc;
}

// ---------------- fused conv: adjacency softmax + SpMM + combine -----------
#define C_SY    0
#define C_SX10  12288
#define C_SX9   24576
#define C_SU    36864      // 8 rows * 3 feats * 12 = 288
#define C_SW    37152      // 144 W0sum | 144 Wf1 | 144 Wb1 | 12 b
#define C_SRED  37600      // 256 * 27
#define C_SRED2 44512      // 8 * 26
#define C_SACC  44720      // 3 * 26
#define C_SMEM_FLOATS 44800

__global__ void __launch_bounds__(256, 1)
conv_kernel(const float* __restrict__ Wf, const float* __restrict__ Wb,
            const float* __restrict__ bvec, float* __restrict__ out) {
    extern __shared__ float sm[];
    float* sY   = sm + C_SY;
    float* sX10 = sm + C_SX10;
    float* sX9  = sm + C_SX9;
    float* sU   = sm + C_SU;
    float* sW   = sm + C_SW;
    float* sRED = sm + C_SRED;
    float* sRED2= sm + C_SRED2;
    float* sACC = sm + C_SACC;

    int tid = threadIdx.x;
    int rowbase = blockIdx.x * 8;

    for (int i = tid; i < 12288 / 4; i += 256) {
        ((float4*)sY)[i]   = ((const float4*)g_Y)[i];
        ((float4*)sX10)[i] = ((const float4*)(g_h3 + 12288))[i];
        ((float4*)sX9)[i]  = ((const float4*)g_h3)[i];
    }
    // FIX (R2): 288 > 256 threads — must stride, or local row 7 reads garbage.
    for (int i = tid; i < 288; i += 256) {
        int r = i / 36, rem = i % 36;
        int c = rem / 12, tau = rem % 12;
        sU[i] = g_U[c * 12288 + (rowbase + r) * 12 + tau];
    }
    if (tid < 144) {
        sW[tid]       = Wf[tid] + Wb[tid];   // k=0: Wf0+Wb0
        sW[144 + tid] = Wf[144 + tid];       // Wf1
        sW[288 + tid] = Wb[144 + tid];       // Wb1
    }
    if (tid < 12) sW[432 + tid] = bvec[tid];
    __syncthreads();

    for (int tile = 0; tile < 4; ++tile) {
        int r0 = tile * 2;   // local rows r0, r0+1
        for (int ap = 0; ap < 3; ++ap) {
            int cidx = (ap == 0) ? 1 : (ap == 1 ? 0 : 2); // a = 10, 9, 11
            const float* sX = (ap == 0) ? sX10 : sX9;
            float u0[12], u1[12];
#pragma unroll
            for (int q = 0; q < 12; ++q) {
                u0[q] = sU[(r0 * 3 + cidx) * 12 + q];
                u1[q] = sU[((r0 + 1) * 3 + cidx) * 12 + q];
            }
            float g0[12], g1[12];
#pragma unroll
            for (int q = 0; q < 12; ++q) { g0[q] = 0.0f; g1[q] = 0.0f; }
            float es0 = 0.0f, es1 = 0.0f;

            for (int j = tid; j < 1024; j += 256) {
                const float4* yr = (const float4*)(sY + j * 12);
                float4 ya = yr[0], yb = yr[1], yc = yr[2];
                float s0 = u0[0]*ya.x + u0[1]*ya.y + u0[2]*ya.z + u0[3]*ya.w
                         + u0[4]*yb.x + u0[5]*yb.y + u0[6]*yb.z + u0[7]*yb.w
                         + u0[8]*yc.x + u0[9]*yc.y + u0[10]*yc.z + u0[11]*yc.w;
                float s1 = u1[0]*ya.x + u1[1]*ya.y + u1[2]*ya.z + u1[3]*ya.w
                         + u1[4]*yb.x + u1[5]*yb.y + u1[6]*yb.z + u1[7]*yb.w
                         + u1[8]*yc.x + u1[9]*yc.y + u1[10]*yc.z + u1[11]*yc.w;
                s0 = (s0 >= 0.05f) ? s0 : 0.0f;
                s1 = (s1 >= 0.05f) ? s1 : 0.0f;
                float e0 = __expf(s0), e1 = __expf(s1);
                es0 += e0; es1 += e1;
                const float4* xr = (const float4*)(sX + j * 12);
                float4 xa = xr[0], xb = xr[1], xc = xr[2];
                g0[0]+=e0*xa.x; g0[1]+=e0*xa.y; g0[2] +=e0*xa.z; g0[3] +=e0*xa.w;
                g0[4]+=e0*xb.x; g0[5]+=e0*xb.y; g0[6] +=e0*xb.z; g0[7] +=e0*xb.w;
                g0[8]+=e0*xc.x; g0[9]+=e0*xc.y; g0[10]+=e0*xc.z; g0[11]+=e0*xc.w;
                g1[0]+=e1*xa.x; g1[1]+=e1*xa.y; g1[2] +=e1*xa.z; g1[3] +=e1*xa.w;
                g1[4]+=e1*xb.x; g1[5]+=e1*xb.y; g1[6] +=e1*xb.z; g1[7] +=e1*xb.w;
                g1[8]+=e1*xc.x; g1[9]+=e1*xc.y; g1[10]+=e1*xc.z; g1[11]+=e1*xc.w;
            }
#pragma unroll
            for (int q = 0; q < 12; ++q) {
                sRED[tid * 27 + q]      = g0[q];
                sRED[tid * 27 + 13 + q] = g1[q];
            }
            sRED[tid * 27 + 12] = es0;
            sRED[tid * 27 + 25] = es1;
            __syncthreads();
            if (tid < 208) {
                int v = tid % 26, chunk = tid / 26;
                float s = 0.0f;
#pragma unroll
                for (int t = 0; t < 32; ++t) s += sRED[(chunk * 32 + t) * 27 + v];
                sRED2[chunk * 26 + v] = s;
            }
            __syncthreads();
            if (tid < 26) {
                float s = 0.0f;
#pragma unroll
                for (int ch = 0; ch < 8; ++ch) s += sRED2[ch * 26 + tid];
                sACC[ap * 26 + tid] = s;
            }
            __syncthreads();
        }
        if (tid < 24) {
            int r = tid / 12, f = tid % 12;
            float inv0 = 1.0f / sACC[0 * 26 + r * 13 + 12];
            float inv1 = 1.0f / sACC[1 * 26 + r * 13 + 12];
            float inv2 = 1.0f / sACC[2 * 26 + r * 13 + 12];
            float acc1 = sW[432 + f], acc2 = sW[432 + f];
#pragma unroll
            for (int q = 0; q < 12; ++q) {
                float ga = sACC[0 * 26 + r * 13 + q] * inv0;
                float gb = sACC[1 * 26 + r * 13 + q] * inv1;
                float gc = sACC[2 * 26 + r * 13 + q] * inv2;
                acc1 += ga * sW[q * 12 + f];
                acc2 += gb * sW[144 + q * 12 + f] + gc * sW[288 + q * 12 + f];
            }
            out[(rowbase + r0 + r) * 12 + f] = fmaxf(acc1, 0.0f) + fmaxf(acc2, 0.0f);
        }
        __syncthreads();
    }
}

// ---------------- launch ----------------
extern "C" void kernel_launch(void* const* d_in, const int* in_sizes, int n_in,
                              void* d_out, int out_size) {
    const float* obs    = (const float*)d_in[0];
    const float* tf     = (const float*)d_in[1];
    const float* fc_w1  = (const float*)d_in[2];
    const float* fc_b1  = (const float*)d_in[3];
    const float* fc_w2  = (const float*)d_in[4];
    const float* fc_b2  = (const float*)d_in[5];
    const float* fc_w3  = (const float*)d_in[6];
    const float* fc_b3  = (const float*)d_in[7];
    const float* Wf     = (const float*)d_in[8];
    const float* Wb     = (const float*)d_in[9];
    const float* bvec   = (const float*)d_in[10];
    const float* li     = (const float*)d_in[11];
    const float* gs_w1  = (const float*)d_in[12];
    const float* gs_b1  = (const float*)d_in[13];
    const float* gs_w2  = (const float*)d_in[14];
    const float* gs_b2  = (const float*)d_in[15];
    const float* gt_w1  = (const float*)d_in[16];
    const float* gt_b1  = (const float*)d_in[17];
    const float* gt_w2  = (const float*)d_in[18];
    const float* gt_b2  = (const float*)d_in[19];
    const float* Bm     = (const float*)d_in[20];
    float* out = (float*)d_out;

    cudaFuncSetAttribute(conv_kernel,
                         cudaFuncAttributeMaxDynamicSharedMemorySize,
                         C_SMEM_FLOATS * sizeof(float));

    prep_kernel<<<224, 256>>>(obs, fc_b1, out);
    small_hidden_kernel<<<13, 256>>>(li, gs_w1, gs_b1, tf, gt_w1, gt_b1);
    u_kernel<<<1024, 96>>>(gs_w2, gs_b2, gt_w2, gt_b2);
    y_kernel<<<48, 256>>>(Bm);

    gemv1_kernel<<<dim3(2, 128), 256>>>(fc_w1, 64);
    act1_kernel<<<16, 256>>>(fc_b2);
    gemv2_kernel<<<dim3(2, 128), 256>>>(fc_w2, 16);
    act2_kernel<<<96, 256>>>(fc_b3);
    gemv3_kernel<<<dim3(12, 32), 256>>>(fc_w3, 64);
    act3_kernel<<<96, 256>>>();

    conv_kernel<<<128, 256, C_SMEM_FLOATS * sizeof(float)>>>(Wf, Wb, bvec, out);
}

// round 4
// speedup vs baseline: 1.9843x; 1.9843x over previous
#include <cuda_runtime.h>
#include <cuda_bf16.h>
#include <cstdint>

// Only Z0[:,:,-1] = conv(X0, t=10) is nonzero in the output.
// Needs: h3 rows t=9,10 ; U feats 9,10,11 ; 3 adjacencies (a=10,9,11 ; c=10).
// Softmax degree-normalization in norm_adj is an exact no-op.

// ---------------- device scratch ----------------
__device__ float g_obs2[2 * 8192];     // MLP input rows t=9,10
__device__ float g_s1[2 * 2048];       // bias-init, gemv1 accumulates (pre-relu)
__device__ float g_s2[2 * 2048];       // bias-init, gemv2 accumulates (pre-relu)
__device__ float g_s3[2 * 12288];      // bias-init, gemv3 accumulates (pre-relu)
                                       // row0 = X9 (1024x12), row1 = X10 (pre-relu)
__device__ float g_sph[12 * 256];      // bias-init, sh accumulates (pre-relu)
__device__ float g_tph[256];           // raw hidden (pre-relu)
__device__ float g_U[3 * 1024 * 12];   // [c][n][tau], c = feat-9 (post-activation)
__device__ float g_Y[1024 * 12];       // Y[n][p] = sum_q B[p,q]*U[n,q,10]

// ---------------- prep: gather obs rows + init all bias accumulators -------
__global__ void prep_kernel(const float* __restrict__ obs,
                            const float* __restrict__ b1,
                            const float* __restrict__ b2,
                            const float* __restrict__ b3,
                            const float* __restrict__ gs_b1,
                            float* __restrict__ out) {
    int idx = blockIdx.x * blockDim.x + threadIdx.x;
    if (idx < 16384) {
        int m = idx >> 13;          // 0 -> t=9, 1 -> t=10
        int k = idx & 8191;         // n*8 + d
        int n = k >> 3, d = k & 7;
        g_obs2[idx] = obs[n * 96 + d * 12 + 9 + m];
        return;
    }
    int i = idx - 16384;
    if (i < 4096) { g_s1[i] = b1[i & 2047]; return; }
    i -= 4096;
    if (i < 36864) { out[12288 + i] = 0.0f; return; }
    i -= 36864;
    if (i < 3072) { g_sph[i] = gs_b1[i & 255]; return; }
    i -= 3072;
    if (i < 4096) { g_s2[i] = b2[i & 2047]; return; }
    i -= 4096;
    if (i < 24576) { g_s3[i] = b3[i % 12288]; return; }
}

// ---------------- split-K GEMV (M=2), optional ReLU on A loads -------------
template<int K, int N, bool RELU>
__device__ __forceinline__ void gemv_body(const float* __restrict__ A,
                                          const float* __restrict__ W,
                                          float* __restrict__ S, int kchunk) {
    int col = (blockIdx.x * blockDim.x + threadIdx.x) * 4;
    int k0  = blockIdx.y * kchunk;
    float a00 = 0, a01 = 0, a02 = 0, a03 = 0;
    float a10 = 0, a11 = 0, a12 = 0, a13 = 0;
#pragma unroll 8
    for (int k = k0; k < k0 + kchunk; ++k) {
        const float4 w = *reinterpret_cast<const float4*>(W + (size_t)k * N + col);
        float x0 = A[k], x1 = A[K + k];
        if (RELU) { x0 = fmaxf(x0, 0.0f); x1 = fmaxf(x1, 0.0f); }
        a00 += x0 * w.x; a01 += x0 * w.y; a02 += x0 * w.z; a03 += x0 * w.w;
        a10 += x1 * w.x; a11 += x1 * w.y; a12 += x1 * w.z; a13 += x1 * w.w;
    }
    atomicAdd(S + col + 0, a00); atomicAdd(S + col + 1, a01);
    atomicAdd(S + col + 2, a02); atomicAdd(S + col + 3, a03);
    atomicAdd(S + N + col + 0, a10); atomicAdd(S + N + col + 1, a11);
    atomicAdd(S + N + col + 2, a12); atomicAdd(S + N + col + 3, a13);
}

__global__ void gemv1_kernel(const float* __restrict__ W, int kchunk) {
    gemv_body<8192, 2048, false>(g_obs2, W, g_s1, kchunk);
}
__global__ void gemv2_kernel(const float* __restrict__ W, int kchunk) {
    gemv_body<2048, 2048, true>(g_s1, W, g_s2, kchunk);
}
__global__ void gemv3_kernel(const float* __restrict__ W, int kchunk) {
    gemv_body<2048, 12288, true>(g_s2, W, g_s3, kchunk);
}

// ---------------- small hidden layers: split-K sph (12x256), tph (256) -----
__global__ void sh_kernel(const float* __restrict__ li,
                          const float* __restrict__ gs_w1,
                          const float* __restrict__ tf,
                          const float* __restrict__ gt_w1,
                          const float* __restrict__ gt_b1) {
    int t = threadIdx.x;
    if (blockIdx.x < 96) {
        int tau = blockIdx.x >> 3, kc = blockIdx.x & 7;
        const float* row = li + tau * 1024 + kc * 128;
        const float* w   = gs_w1 + (size_t)(kc * 128) * 256 + t;
        float acc = 0.0f;
#pragma unroll 16
        for (int k = 0; k < 128; ++k) acc += row[k] * w[(size_t)k * 256];
        atomicAdd(&g_sph[tau * 256 + t], acc);
    } else {
        float acc = 0.0f;
#pragma unroll
        for (int k = 0; k < 36; ++k) acc += tf[k] * gt_w1[k * 256 + t];
        g_tph[t] = acc + gt_b1[t];   // pre-relu
    }
}

// ---------------- U features 9,10,11 : 1024 blocks x 96 threads ------------
__global__ void u_kernel(const float* __restrict__ gs_w2,
                         const float* __restrict__ gs_b2,
                         const float* __restrict__ gt_w2,
                         const float* __restrict__ gt_b2) {
    int n = blockIdx.x;
    int c = threadIdx.x >> 5;       // 0..2 -> feats 9..11
    int lane = threadIdx.x & 31;
    int j = n * 12 + 9 + c;
    float wg[8], wt[8];
#pragma unroll
    for (int i = 0; i < 8; ++i) {
        int k = lane + 32 * i;
        wg[i] = gs_w2[(size_t)k * 12288 + j];
        wt[i] = gt_w2[(size_t)k * 12288 + j];
    }
    float tp = 0.0f;
#pragma unroll
    for (int i = 0; i < 8; ++i) tp += fmaxf(g_tph[lane + 32 * i], 0.0f) * wt[i];
#pragma unroll
    for (int o = 16; o; o >>= 1) tp += __shfl_xor_sync(0xffffffff, tp, o);
    float tpv = fmaxf(tp + gt_b2[j], 0.0f);
    float bsp = gs_b2[j];
#pragma unroll
    for (int tau = 0; tau < 12; ++tau) {
        float sp = 0.0f;
#pragma unroll
        for (int i = 0; i < 8; ++i)
            sp += fmaxf(g_sph[tau * 256 + lane + 32 * i], 0.0f) * wg[i];
#pragma unroll
        for (int o = 16; o; o >>= 1) sp += __shfl_xor_sync(0xffffffff, sp, o);
        if (lane == 0)
            g_U[c * 12288 + n * 12 + tau] = fmaxf(sp + bsp, 0.0f) + tpv;
    }
}

// ---------------- Y = U_10 @ B^T ----------------
__global__ void y_kernel(const float* __restrict__ Bm) {
    int idx = blockIdx.x * blockDim.x + threadIdx.x;
    if (idx >= 12288) return;
    int n = idx / 12, p = idx % 12;
    float acc = 0.0f;
#pragma unroll
    for (int q = 0; q < 12; ++q)
        acc += Bm[p * 12 + q] * g_U[12288 + n * 12 + q];
    g_Y[idx] = acc;
}

// ---------------- fused conv: adjacency softmax + SpMM + combine -----------
#define C_SY    0
#define C_SX10  12288
#define C_SX9   24576
#define C_SU    36864      // 8 rows * 3 feats * 12 = 288
#define C_SW    37152      // 144 W0sum | 144 Wf1 | 144 Wb1 | 12 b
#define C_SRED  37600      // 256 * 27
#define C_SRED2 44512      // 8 * 26
#define C_SACC  44720      // 3 * 26
#define C_SMEM_FLOATS 44800

__device__ __forceinline__ float4 relu4(float4 v) {
    v.x = fmaxf(v.x, 0.0f); v.y = fmaxf(v.y, 0.0f);
    v.z = fmaxf(v.z, 0.0f); v.w = fmaxf(v.w, 0.0f);
    return v;
}

__global__ void __launch_bounds__(256, 1)
conv_kernel(const float* __restrict__ Wf, const float* __restrict__ Wb,
            const float* __restrict__ bvec, float* __restrict__ out) {
    extern __shared__ float sm[];
    float* sY   = sm + C_SY;
    float* sX10 = sm + C_SX10;
    float* sX9  = sm + C_SX9;
    float* sU   = sm + C_SU;
    float* sW   = sm + C_SW;
    float* sRED = sm + C_SRED;
    float* sRED2= sm + C_SRED2;
    float* sACC = sm + C_SACC;

    int tid = threadIdx.x;
    int rowbase = blockIdx.x * 8;

    for (int i = tid; i < 12288 / 4; i += 256) {
        ((float4*)sY)[i]   = ((const float4*)g_Y)[i];
        ((float4*)sX10)[i] = relu4(((const float4*)(g_s3 + 12288))[i]);  // relu fused
        ((float4*)sX9)[i]  = relu4(((const float4*)g_s3)[i]);
    }
    for (int i = tid; i < 288; i += 256) {          // 288 > 256: must stride
        int r = i / 36, rem = i % 36;
        int c = rem / 12, tau = rem % 12;
        sU[i] = g_U[c * 12288 + (rowbase + r) * 12 + tau];
    }
    if (tid < 144) {
        sW[tid]       = Wf[tid] + Wb[tid];   // k=0: Wf0+Wb0
        sW[144 + tid] = Wf[144 + tid];       // Wf1
        sW[288 + tid] = Wb[144 + tid];       // Wb1
    }
    if (tid < 12) sW[432 + tid] = bvec[tid];
    __syncthreads();

    for (int tile = 0; tile < 4; ++tile) {
        int r0 = tile * 2;   // local rows r0, r0+1
        for (int ap = 0; ap < 3; ++ap) {
            int cidx = (ap == 0) ? 1 : (ap == 1 ? 0 : 2); // a = 10, 9, 11
            const float* sX = (ap == 0) ? sX10 : sX9;
            float u0[12], u1[12];
#pragma unroll
            for (int q = 0; q < 12; ++q) {
                u0[q] = sU[(r0 * 3 + cidx) * 12 + q];
                u1[q] = sU[((r0 + 1) * 3 + cidx) * 12 + q];
            }
            float g0[12], g1[12];
#pragma unroll
            for (int q = 0; q < 12; ++q) { g0[q] = 0.0f; g1[q] = 0.0f; }
            float es0 = 0.0f, es1 = 0.0f;

            for (int j = tid; j < 1024; j += 256) {
                const float4* yr = (const float4*)(sY + j * 12);
                float4 ya = yr[0], yb = yr[1], yc = yr[2];
                float s0 = u0[0]*ya.x + u0[1]*ya.y + u0[2]*ya.z + u0[3]*ya.w
                         + u0[4]*yb.x + u0[5]*yb.y + u0[6]*yb.z + u0[7]*yb.w
                         + u0[8]*yc.x + u0[9]*yc.y + u0[10]*yc.z + u0[11]*yc.w;
                float s1 = u1[0]*ya.x + u1[1]*ya.y + u1[2]*ya.z + u1[3]*ya.w
                         + u1[4]*yb.x + u1[5]*yb.y + u1[6]*yb.z + u1[7]*yb.w
                         + u1[8]*yc.x + u1[9]*yc.y + u1[10]*yc.z + u1[11]*yc.w;
                s0 = (s0 >= 0.05f) ? s0 : 0.0f;
                s1 = (s1 >= 0.05f) ? s1 : 0.0f;
                float e0 = __expf(s0), e1 = __expf(s1);
                es0 += e0; es1 += e1;
                const float4* xr = (const float4*)(sX + j * 12);
                float4 xa = xr[0], xb = xr[1], xc = xr[2];
                g0[0]+=e0*xa.x; g0[1]+=e0*xa.y; g0[2] +=e0*xa.z; g0[3] +=e0*xa.w;
                g0[4]+=e0*xb.x; g0[5]+=e0*xb.y; g0[6] +=e0*xb.z; g0[7] +=e0*xb.w;
                g0[8]+=e0*xc.x; g0[9]+=e0*xc.y; g0[10]+=e0*xc.z; g0[11]+=e0*xc.w;
                g1[0]+=e1*xa.x; g1[1]+=e1*xa.y; g1[2] +=e1*xa.z; g1[3] +=e1*xa.w;
                g1[4]+=e1*xb.x; g1[5]+=e1*xb.y; g1[6] +=e1*xb.z; g1[7] +=e1*xb.w;
                g1[8]+=e1*xc.x; g1[9]+=e1*xc.y; g1[10]+=e1*xc.z; g1[11]+=e1*xc.w;
            }
#pragma unroll
            for (int q = 0; q < 12; ++q) {
                sRED[tid * 27 + q]      = g0[q];
                sRED[tid * 27 + 13 + q] = g1[q];
            }
            sRED[tid * 27 + 12] = es0;
            sRED[tid * 27 + 25] = es1;
            __syncthreads();
            if (tid < 208) {
                int v = tid % 26, chunk = tid / 26;
                float s = 0.0f;
#pragma unroll
                for (int t = 0; t < 32; ++t) s += sRED[(chunk * 32 + t) * 27 + v];
                sRED2[chunk * 26 + v] = s;
            }
            __syncthreads();
            if (tid < 26) {
                float s = 0.0f;
#pragma unroll
                for (int ch = 0; ch < 8; ++ch) s += sRED2[ch * 26 + tid];
                sACC[ap * 26 + tid] = s;
            }
            __syncthreads();
        }
        if (tid < 24) {
            int r = tid / 12, f = tid % 12;
            float inv0 = 1.0f / sACC[0 * 26 + r * 13 + 12];
            float inv1 = 1.0f / sACC[1 * 26 + r * 13 + 12];
            float inv2 = 1.0f / sACC[2 * 26 + r * 13 + 12];
            float acc1 = sW[432 + f], acc2 = sW[432 + f];
#pragma unroll
            for (int q = 0; q < 12; ++q) {
                float ga = sACC[0 * 26 + r * 13 + q] * inv0;
                float gb = sACC[1 * 26 + r * 13 + q] * inv1;
                float gc = sACC[2 * 26 + r * 13 + q] * inv2;
                acc1 += ga * sW[q * 12 + f];
                acc2 += gb * sW[144 + q * 12 + f] + gc * sW[288 + q * 12 + f];
            }
            out[(rowbase + r0 + r) * 12 + f] = fmaxf(acc1, 0.0f) + fmaxf(acc2, 0.0f);
        }
        __syncthreads();
    }
}

// ---------------- launch ----------------
extern "C" void kernel_launch(void* const* d_in, const int* in_sizes, int n_in,
                              void* d_out, int out_size) {
    const float* obs    = (const float*)d_in[0];
    const float* tf     = (const float*)d_in[1];
    const float* fc_w1  = (const float*)d_in[2];
    const float* fc_b1  = (const float*)d_in[3];
    const float* fc_w2  = (const float*)d_in[4];
    const float* fc_b2  = (const float*)d_in[5];
    const float* fc_w3  = (const float*)d_in[6];
    const float* fc_b3  = (const float*)d_in[7];
    const float* Wf     = (const float*)d_in[8];
    const float* Wb     = (const float*)d_in[9];
    const float* bvec   = (const float*)d_in[10];
    const float* li     = (const float*)d_in[11];
    const float* gs_w1  = (const float*)d_in[12];
    const float* gs_b1  = (const float*)d_in[13];
    const float* gs_w2  = (const float*)d_in[14];
    const float* gs_b2  = (const float*)d_in[15];
    const float* gt_w1  = (const float*)d_in[16];
    const float* gt_b1  = (const float*)d_in[17];
    const float* gt_w2  = (const float*)d_in[18];
    const float* gt_b2  = (const float*)d_in[19];
    const float* Bm     = (const float*)d_in[20];
    float* out = (float*)d_out;

    cudaFuncSetAttribute(conv_kernel,
                         cudaFuncAttributeMaxDynamicSharedMemorySize,
                         C_SMEM_FLOATS * sizeof(float));

    prep_kernel<<<348, 256>>>(obs, fc_b1, fc_b2, fc_b3, gs_b1, out);
    sh_kernel<<<97, 256>>>(li, gs_w1, tf, gt_w1, gt_b1);
    u_kernel<<<1024, 96>>>(gs_w2, gs_b2, gt_w2, gt_b2);
    y_kernel<<<48, 256>>>(Bm);

    gemv1_kernel<<<dim3(2, 128), 256>>>(fc_w1, 64);
    gemv2_kernel<<<dim3(2, 128), 256>>>(fc_w2, 16);
    gemv3_kernel<<<dim3(12, 32), 256>>>(fc_w3, 64);

    conv_kernel<<<128, 256, C_SMEM_FLOATS * sizeof(float)>>>(Wf, Wb, bvec, out);
}